// round 2
// baseline (speedup 1.0000x reference)
#include <cuda_runtime.h>
#include <cstdint>

// ---------------- problem constants ----------------
#define TT       128      // edges per CTA tile
#define THREADS  256
#define PADT     129      // TT + 1 (bank-conflict pad)
#define DD       128      // node feature dim
#define INF      256      // 2*D
#define HID      128
#define LAT      5
#define BETA     10.0f
#define V2C      3.5f

// scalar accumulators (scratch — no allocations allowed)
__device__ double g_rsum;
__device__ double g_klsum;

struct Params {
    const float* x;
    const int*   row;
    const int*   col;
    const float* eps;
    const float *eW0, *eb0, *eW1, *eb1, *eW2, *eb2, *eW3, *eb3;
    const float *dW0, *db0, *dW1, *db1, *dW2, *db2, *dW3, *db3;
    float*       out;
    int          E;
};

__global__ void zero_kernel() { g_rsum = 0.0; g_klsum = 0.0; }

__global__ void fin_kernel(float* out, int E) {
    out[E]     = (float)(g_rsum  / (double)E);
    out[E + 1] = (float)(g_klsum / ((double)E * (double)LAT));
}

// ---------------------------------------------------------------------------
// Micro-GEMM: C[128 x 128] += A_src[K x 128] (col = edge) * W[K x 128-view]
// A_src stored k-major with row stride PADT. W view: W[k*wstride + n], n<128.
// Each thread (16x16 grid) owns an 8x8 C micro-tile. Bs is a 32x128 stage.
// Pattern per slab: load Bs -> sync -> FMA -> sync  (Bs reuse is safe).
// ---------------------------------------------------------------------------
__device__ __forceinline__ void gemm_acc(
    const float* __restrict__ W, int wstride, int K,
    const float* __restrict__ Asrc, float* __restrict__ Bs,
    float c[8][8], int tid)
{
    const int t0 = (tid >> 4) * 8;
    const int n0 = (tid & 15) * 8;

    for (int k0 = 0; k0 < K; k0 += 32) {
        const int KT = min(32, K - k0);
        // stage weight slab (coalesced: n contiguous)
        for (int idx = tid; idx < KT * 128; idx += THREADS) {
            int kk = idx >> 7, n = idx & 127;
            Bs[idx] = W[(size_t)(k0 + kk) * wstride + n];
        }
        __syncthreads();

        #pragma unroll 4
        for (int kk = 0; kk < KT; kk++) {
            float a[8], b[8];
            const float* Ar = Asrc + (size_t)(k0 + kk) * PADT + t0;
            const float* Br = Bs + kk * 128 + n0;
            #pragma unroll
            for (int i = 0; i < 8; i++) a[i] = Ar[i];
            #pragma unroll
            for (int j = 0; j < 8; j++) b[j] = Br[j];
            #pragma unroll
            for (int i = 0; i < 8; i++)
                #pragma unroll
                for (int j = 0; j < 8; j++)
                    c[i][j] = fmaf(a[i], b[j], c[i][j]);
        }
        __syncthreads();
    }
}

__device__ __forceinline__ void init_bias(float c[8][8], const float* __restrict__ b, int tid) {
    const int n0 = (tid & 15) * 8;
    #pragma unroll
    for (int j = 0; j < 8; j++) {
        float bv = b[n0 + j];
        #pragma unroll
        for (int i = 0; i < 8; i++) c[i][j] = bv;
    }
}

template <bool RELU>
__device__ __forceinline__ void writeback(float c[8][8], float* __restrict__ Adst, int tid) {
    const int t0 = (tid >> 4) * 8;
    const int n0 = (tid & 15) * 8;
    #pragma unroll
    for (int i = 0; i < 8; i++)
        #pragma unroll
        for (int j = 0; j < 8; j++) {
            float v = c[i][j];
            if (RELU) v = fmaxf(v, 0.0f);
            Adst[(size_t)(n0 + j) * PADT + t0 + i] = v;
        }
    __syncthreads();
}

// ---------------------------------------------------------------------------
// Fused VAE kernel: one CTA = one tile of 128 edges.
// SMEM: A0 (256 rows) | A1 (128 rows) | Bs (32x128) | idx | rloss | klp
// ---------------------------------------------------------------------------
__global__ void __launch_bounds__(THREADS, 1)
vae_kernel(Params p)
{
    extern __shared__ float smem[];
    float* A0     = smem;                        // 256 * PADT
    float* A1     = smem + 256 * PADT;           // 128 * PADT
    float* Bs     = smem + 384 * PADT;           // 4096
    int*   rows_s = (int*)(Bs + 4096);           // 128
    int*   cols_s = rows_s + TT;                 // 128
    float* rloss  = (float*)(cols_s + TT);       // 128
    float* klp    = rloss + TT;                  // 128

    const int tid   = threadIdx.x;
    const int e0    = blockIdx.x * TT;
    const int valid = min(TT, p.E - e0);

    if (tid < TT) {
        int t = tid;
        int e = e0 + t;
        rows_s[t] = (t < valid) ? p.row[e] : 0;
        cols_s[t] = (t < valid) ? p.col[e] : 0;
        rloss[t]  = 0.0f;
    }
    __syncthreads();

    // ---- gather pair -> A0[k][t], k in [0,256). invalid edges -> 0 ----
    for (int base = 0; base < TT; base += 4) {
        int t = base + (tid >> 6);
        int q = tid & 63;                       // float4 idx within 256 floats
        int node = (q < 32) ? rows_s[t] : cols_s[t];
        int qq = q & 31;
        float4 v = make_float4(0.f, 0.f, 0.f, 0.f);
        if (t < valid)
            v = reinterpret_cast<const float4*>(p.x + (size_t)node * DD)[qq];
        int kb = q * 4;
        A0[(size_t)(kb + 0) * PADT + t] = v.x;
        A0[(size_t)(kb + 1) * PADT + t] = v.y;
        A0[(size_t)(kb + 2) * PADT + t] = v.z;
        A0[(size_t)(kb + 3) * PADT + t] = v.w;
    }
    __syncthreads();

    float c[8][8];

    // ---- encoder ----
    init_bias(c, p.eb0, tid);  gemm_acc(p.eW0, HID, INF, A0, Bs, c, tid);  writeback<true>(c, A1, tid);
    init_bias(c, p.eb1, tid);  gemm_acc(p.eW1, HID, HID, A1, Bs, c, tid);  writeback<true>(c, A0, tid);
    init_bias(c, p.eb2, tid);  gemm_acc(p.eW2, HID, HID, A0, Bs, c, tid);  writeback<true>(c, A1, tid);

    // ---- e3 (128 -> 10) + reparameterize + KL, z -> A0 rows [0,5) ----
    for (int idx = tid; idx < HID * 10; idx += THREADS) Bs[idx] = p.eW3[idx];
    __syncthreads();

    if (tid < TT) {
        int t = tid;
        float s[10];
        #pragma unroll
        for (int l = 0; l < 10; l++) s[l] = p.eb3[l];
        for (int k = 0; k < HID; k++) {
            float a = A1[(size_t)k * PADT + t];
            #pragma unroll
            for (int l = 0; l < 10; l++) s[l] = fmaf(a, Bs[k * 10 + l], s[l]);
        }
        float kls = 0.0f;
        int e = e0 + t;
        #pragma unroll
        for (int l = 0; l < LAT; l++) {
            float mu = s[l], lv = s[LAT + l];
            float z = 0.0f;
            if (t < valid) {
                float ep = p.eps[(size_t)e * LAT + l];
                z = fmaf(ep, expf(0.5f * lv), mu);
                kls += -0.5f * (1.0f + lv - mu * mu - expf(lv));
            }
            A0[(size_t)l * PADT + t] = z;
        }
        klp[t] = kls * BETA;
    }
    __syncthreads();

    // ---- decoder ----
    init_bias(c, p.db0, tid);  gemm_acc(p.dW0, HID, LAT, A0, Bs, c, tid);  writeback<true>(c, A1, tid);
    init_bias(c, p.db1, tid);  gemm_acc(p.dW1, HID, HID, A1, Bs, c, tid);  writeback<true>(c, A0, tid);
    init_bias(c, p.db2, tid);  gemm_acc(p.dW2, HID, HID, A0, Bs, c, tid);  writeback<true>(c, A1, tid);

    // ---- d3 (128 -> 256) in two 128-col halves, fused recon-loss epilogue ----
    const int t0 = (tid >> 4) * 8;
    const int n0 = (tid & 15) * 8;
    for (int h = 0; h < 2; h++) {
        init_bias(c, p.db3 + h * 128, tid);
        gemm_acc(p.dW3 + h * 128, INF, HID, A1, Bs, c, tid);
        const int* nodes = (h == 0) ? rows_s : cols_s;
        #pragma unroll
        for (int i = 0; i < 8; i++) {
            int t = t0 + i;
            if (t < valid) {
                const float* xr = p.x + (size_t)nodes[t] * DD + n0;
                float part = 0.0f;
                #pragma unroll
                for (int j = 0; j < 8; j++) {
                    float d = c[i][j] - xr[j];
                    part = fmaf(d, d, part);
                }
                atomicAdd(&rloss[t], part);
            }
        }
        __syncthreads();
    }

    // ---- affinities + scalar reductions ----
    if (tid < TT) {
        int t = tid;
        float rl = 0.0f;
        if (t < valid) {
            rl = sqrtf(rloss[t]);
            p.out[e0 + t] = 1.0f / fmaf(V2C, rl, 1.0f);
        }
        rloss[t] = rl;
    }
    __syncthreads();

    if (tid == 0) {
        float rs = 0.0f, ks = 0.0f;
        for (int t = 0; t < valid; t++) { rs += rloss[t]; ks += klp[t]; }
        atomicAdd(&g_rsum,  (double)rs);
        atomicAdd(&g_klsum, (double)ks);
    }
}

// ---------------------------------------------------------------------------
extern "C" void kernel_launch(void* const* d_in, const int* in_sizes, int n_in,
                              void* d_out, int out_size)
{
    Params p;
    p.x   = (const float*)d_in[0];
    p.row = (const int*)  d_in[1];
    p.col = (const int*)  d_in[2];
    p.eps = (const float*)d_in[3];
    p.eW0 = (const float*)d_in[4];   p.eb0 = (const float*)d_in[5];
    p.eW1 = (const float*)d_in[6];   p.eb1 = (const float*)d_in[7];
    p.eW2 = (const float*)d_in[8];   p.eb2 = (const float*)d_in[9];
    p.eW3 = (const float*)d_in[10];  p.eb3 = (const float*)d_in[11];
    p.dW0 = (const float*)d_in[12];  p.db0 = (const float*)d_in[13];
    p.dW1 = (const float*)d_in[14];  p.db1 = (const float*)d_in[15];
    p.dW2 = (const float*)d_in[16];  p.db2 = (const float*)d_in[17];
    p.dW3 = (const float*)d_in[18];  p.db3 = (const float*)d_in[19];
    p.out = (float*)d_out;
    p.E   = in_sizes[1];             // edge count (row array)

    const size_t smem_bytes =
        (size_t)(384 * PADT + 4096) * sizeof(float)   // A0+A1 + Bs
        + 2 * TT * sizeof(int)                        // rows, cols
        + 2 * TT * sizeof(float);                     // rloss, klp

    cudaFuncSetAttribute(vae_kernel,
                         cudaFuncAttributeMaxDynamicSharedMemorySize,
                         (int)smem_bytes);

    const int tiles = (p.E + TT - 1) / TT;

    zero_kernel<<<1, 1>>>();
    vae_kernel<<<tiles, THREADS, smem_bytes>>>(p);
    fin_kernel<<<1, 1>>>((float*)d_out, p.E);
}

// round 4
// speedup vs baseline: 2.3227x; 2.3227x over previous
#include <cuda_runtime.h>
#include <cuda_bf16.h>
#include <cstdint>

#define THREADS 256
#define TT      128
#define STRIDE  136                 // bf16 elems per smem row (128 + 8 pad)
#define TSZ     (128 * STRIDE)      // elems per weight tile (17408)
#define BETA    10.0f
#define V2C     3.5f

__device__ double g_rsum, g_klsum;

// 10 weight tiles, bf16 hi/lo, [k][n] layout with row stride 136
enum { T_E0A, T_E0B, T_E1, T_E2, T_E3, T_D0, T_D1, T_D2, T_D3A, T_D3B };
__device__ __align__(16) uint16_t g_whi[10 * TSZ];
__device__ __align__(16) uint16_t g_wlo[10 * TSZ];

// ---- smem byte offsets ----
#define AHI       0
#define ALO       34816
#define SLOT_HI(s) (69632 + (s) * 69632)
#define SLOT_LO(s) (69632 + (s) * 69632 + 34816)
#define BIASO(b)  (208896 + (b) * 512)     // 2 x 128 floats
#define TMPB      209920                   // 128 x 16 floats
#define ROWS_S    218112
#define COLS_S    218624
#define KLP       219136
#define RS        219648
#define RED       220160
#define SMEM_TOTAL 220256

struct Params {
    const float* x; const int* row; const int* col; const float* eps;
    const float *eW0,*eb0,*eW1,*eb1,*eW2,*eb2,*eW3,*eb3;
    const float *dW0,*db0,*dW1,*db1,*dW2,*db2,*dW3,*db3;
    float* out; int E;
};

// ---- helpers ----
__device__ __forceinline__ uint32_t smem_u32(const void* p) {
    uint32_t a;
    asm("{ .reg .u64 t; cvta.to.shared.u64 t, %1; cvt.u32.u64 %0, t; }" : "=r"(a) : "l"(p));
    return a;
}

__device__ __forceinline__ void split2(float a, float b, uint32_t& h, uint32_t& l) {
    __nv_bfloat16 ah = __float2bfloat16(a);
    __nv_bfloat16 bh = __float2bfloat16(b);
    __nv_bfloat16 al = __float2bfloat16(a - __bfloat162float(ah));
    __nv_bfloat16 bl = __float2bfloat16(b - __bfloat162float(bh));
    h = (uint32_t)__bfloat16_as_ushort(ah) | ((uint32_t)__bfloat16_as_ushort(bh) << 16);
    l = (uint32_t)__bfloat16_as_ushort(al) | ((uint32_t)__bfloat16_as_ushort(bl) << 16);
}

// A fragment: 16x16 row-major tile at (m0, k0) via ldmatrix.x4
__device__ __forceinline__ void lda4(uint32_t a[4], uint32_t base, int m0, int k0, int lane) {
    uint32_t addr = base + (uint32_t)(((m0 + (lane & 7) + ((lane & 8) ? 8 : 0)) * STRIDE
                                   + k0 + ((lane & 16) ? 8 : 0)) << 1);
    asm volatile("ldmatrix.sync.aligned.m8n8.x4.shared.b16 {%0,%1,%2,%3}, [%4];"
        : "=r"(a[0]), "=r"(a[1]), "=r"(a[2]), "=r"(a[3]) : "r"(addr));
}

// B fragments: 16(k) x 16(n) tile at (k0, n0) via ldmatrix.x4.trans
// -> b[0..1] = frag cols n0..n0+7, b[2..3] = frag cols n0+8..n0+15
__device__ __forceinline__ void ldb4t(uint32_t b[4], uint32_t base, int k0, int n0, int lane) {
    uint32_t addr = base + (uint32_t)(((k0 + (lane & 7) + ((lane & 8) ? 8 : 0)) * STRIDE
                                   + n0 + ((lane & 16) ? 8 : 0)) << 1);
    asm volatile("ldmatrix.sync.aligned.m8n8.x4.trans.shared.b16 {%0,%1,%2,%3}, [%4];"
        : "=r"(b[0]), "=r"(b[1]), "=r"(b[2]), "=r"(b[3]) : "r"(addr));
}

__device__ __forceinline__ void mma16816(float* c, const uint32_t a[4], uint32_t b0, uint32_t b1) {
    asm volatile("mma.sync.aligned.m16n8k16.row.col.f32.bf16.bf16.f32 "
        "{%0,%1,%2,%3}, {%4,%5,%6,%7}, {%8,%9}, {%0,%1,%2,%3};"
        : "+f"(c[0]), "+f"(c[1]), "+f"(c[2]), "+f"(c[3])
        : "r"(a[0]), "r"(a[1]), "r"(a[2]), "r"(a[3]), "r"(b0), "r"(b1));
}

// 3-pass split GEMM: c[16 rows x 128 cols per warp] += A(hi+lo) * B(hi+lo), drop lo*lo
template<int KS, int NT2>
__device__ __forceinline__ void pass3(float c[64], uint32_t sb,
                                      uint32_t bhi, uint32_t blo, int m0, int lane) {
    #pragma unroll 2
    for (int ks = 0; ks < KS; ks++) {
        uint32_t ah[4], al[4];
        lda4(ah, sb + AHI, m0, ks * 16, lane);
        lda4(al, sb + ALO, m0, ks * 16, lane);
        #pragma unroll
        for (int q = 0; q < NT2; q++) {
            uint32_t bh[4], bl[4];
            ldb4t(bh, bhi, ks * 16, q * 16, lane);
            ldb4t(bl, blo, ks * 16, q * 16, lane);
            float* c0 = c + q * 8;
            float* c1 = c + q * 8 + 4;
            mma16816(c0, ah, bh[0], bh[1]);  mma16816(c1, ah, bh[2], bh[3]);
            mma16816(c0, al, bh[0], bh[1]);  mma16816(c1, al, bh[2], bh[3]);
            mma16816(c0, ah, bl[0], bl[1]);  mma16816(c1, ah, bl[2], bl[3]);
        }
    }
}

__device__ __forceinline__ void zero64(float c[64]) {
    #pragma unroll
    for (int i = 0; i < 64; i++) c[i] = 0.f;
}

__device__ __forceinline__ void copy_tile(uint8_t* sm, int slot, int t, int tid) {
    const uint4* sh = (const uint4*)(g_whi + (size_t)t * TSZ);
    const uint4* sl = (const uint4*)(g_wlo + (size_t)t * TSZ);
    uint4* dh = (uint4*)(sm + SLOT_HI(slot));
    uint4* dl = (uint4*)(sm + SLOT_LO(slot));
    for (int i = tid; i < TSZ / 8; i += THREADS) { dh[i] = sh[i]; dl[i] = sl[i]; }
}

// gather x[node] rows into A tile (split bf16); 2 threads per row
__device__ __forceinline__ void gather(uint8_t* sm, const float* x, const int* nodes,
                                       int e0, int E, int tid) {
    int r = tid >> 1, half = tid & 1;
    bool v = (e0 + r) < E;
    int node = nodes[r];
    const float4* xr = (const float4*)(x + (size_t)node * 128 + half * 64);
    uint8_t* hp = sm + AHI + (size_t)(r * STRIDE + half * 64) * 2;
    uint8_t* lp = sm + ALO + (size_t)(r * STRIDE + half * 64) * 2;
    #pragma unroll
    for (int i = 0; i < 16; i++) {
        float4 f = v ? xr[i] : make_float4(0.f, 0.f, 0.f, 0.f);
        uint32_t h0, l0, h1, l1;
        split2(f.x, f.y, h0, l0);
        split2(f.z, f.w, h1, l1);
        *(uint2*)(hp + i * 8) = make_uint2(h0, h1);
        *(uint2*)(lp + i * 8) = make_uint2(l0, l1);
    }
}

// bias + relu + split -> A tile
__device__ __forceinline__ void epi_hidden(const float c[64], uint8_t* sm,
                                           const float* bias, int m0, int lane) {
    int g = lane >> 2, qp = lane & 3;
    int r0 = m0 + g, r1 = m0 + g + 8;
    #pragma unroll
    for (int nt = 0; nt < 16; nt++) {
        int col = nt * 8 + qp * 2;
        float b0 = bias[col], b1 = bias[col + 1];
        float v0 = fmaxf(c[nt*4+0] + b0, 0.f), v1 = fmaxf(c[nt*4+1] + b1, 0.f);
        float v2 = fmaxf(c[nt*4+2] + b0, 0.f), v3 = fmaxf(c[nt*4+3] + b1, 0.f);
        uint32_t h, l;
        split2(v0, v1, h, l);
        *(uint32_t*)(sm + AHI + (size_t)(r0 * STRIDE + col) * 2) = h;
        *(uint32_t*)(sm + ALO + (size_t)(r0 * STRIDE + col) * 2) = l;
        split2(v2, v3, h, l);
        *(uint32_t*)(sm + AHI + (size_t)(r1 * STRIDE + col) * 2) = h;
        *(uint32_t*)(sm + ALO + (size_t)(r1 * STRIDE + col) * 2) = l;
    }
}

// recon ssq epilogue for one d3 half
__device__ __forceinline__ void epi_recon(const float c[64], uint8_t* sm, const float* bias,
                                          const float* x, const int* nodes, int m0, int lane) {
    int g = lane >> 2, qp = lane & 3;
    int r0 = m0 + g, r1 = r0 + 8;
    const float* x0 = x + (size_t)nodes[r0] * 128;
    const float* x1 = x + (size_t)nodes[r1] * 128;
    float s0 = 0.f, s1 = 0.f;
    #pragma unroll
    for (int nt = 0; nt < 16; nt++) {
        int col = nt * 8 + qp * 2;
        float b0 = bias[col], b1 = bias[col + 1];
        float2 xa = *(const float2*)(x0 + col);
        float2 xb = *(const float2*)(x1 + col);
        float d0 = c[nt*4+0] + b0 - xa.x, d1 = c[nt*4+1] + b1 - xa.y;
        float d2 = c[nt*4+2] + b0 - xb.x, d3 = c[nt*4+3] + b1 - xb.y;
        s0 = fmaf(d0, d0, fmaf(d1, d1, s0));
        s1 = fmaf(d2, d2, fmaf(d3, d3, s1));
    }
    s0 += __shfl_xor_sync(0xFFFFFFFFu, s0, 1);
    s0 += __shfl_xor_sync(0xFFFFFFFFu, s0, 2);
    s1 += __shfl_xor_sync(0xFFFFFFFFu, s1, 1);
    s1 += __shfl_xor_sync(0xFFFFFFFFu, s1, 2);
    if (qp == 0) {
        float* rs = (float*)(sm + RS);
        rs[r0] += s0;
        rs[r1] += s1;
    }
}

// ---- weight prep ----
__device__ void prep_one(const float* W, int krows, int kstride, int noff, int ncols, int tile) {
    int total = krows * ncols;
    int gt = blockIdx.x * blockDim.x + threadIdx.x;
    int gs = gridDim.x * blockDim.x;
    for (int idx = gt; idx < total; idx += gs) {
        int k = idx / ncols, n = idx % ncols;
        float w = W[(size_t)k * kstride + noff + n];
        __nv_bfloat16 h = __float2bfloat16(w);
        __nv_bfloat16 l = __float2bfloat16(w - __bfloat162float(h));
        size_t o = (size_t)tile * TSZ + (size_t)k * STRIDE + n;
        g_whi[o] = __bfloat16_as_ushort(h);
        g_wlo[o] = __bfloat16_as_ushort(l);
    }
}

__global__ void prep_kernel(Params p) {
    if (blockIdx.x == 0 && threadIdx.x == 0) { g_rsum = 0.0; g_klsum = 0.0; }
    prep_one(p.eW0,             128, 128, 0,   128, T_E0A);
    prep_one(p.eW0 + 128 * 128, 128, 128, 0,   128, T_E0B);
    prep_one(p.eW1,             128, 128, 0,   128, T_E1);
    prep_one(p.eW2,             128, 128, 0,   128, T_E2);
    prep_one(p.eW3,             128, 10,  0,   10,  T_E3);
    prep_one(p.dW0,             5,   128, 0,   128, T_D0);
    prep_one(p.dW1,             128, 128, 0,   128, T_D1);
    prep_one(p.dW2,             128, 128, 0,   128, T_D2);
    prep_one(p.dW3,             128, 256, 0,   128, T_D3A);
    prep_one(p.dW3,             128, 256, 128, 128, T_D3B);
}

__global__ void fin_kernel(float* out, int E) {
    out[E]     = (float)(g_rsum  / (double)E);
    out[E + 1] = (float)(g_klsum / ((double)E * 5.0));
}

// ---- main fused VAE kernel: 1 CTA = 128 edges, 8 warps (16 rows each) ----
__global__ void __launch_bounds__(THREADS, 1)
vae_kernel(Params p) {
    extern __shared__ __align__(16) uint8_t sm[];
    const uint32_t sb = smem_u32(sm);
    const int tid  = threadIdx.x;
    const int lane = tid & 31;
    const int m0   = (tid >> 5) * 16;
    const int e0   = blockIdx.x * TT;

    int* rows_s = (int*)(sm + ROWS_S);
    int* cols_s = (int*)(sm + COLS_S);
    if (tid < 128) {
        int e = e0 + tid;
        bool v = e < p.E;
        rows_s[tid] = v ? p.row[e] : 0;
        cols_s[tid] = v ? p.col[e] : 0;
        ((float*)(sm + RS))[tid] = 0.f;
    }
    copy_tile(sm, 0, T_E0A, tid);
    __syncthreads();

    gather(sm, p.x, rows_s, e0, p.E, tid);
    if (tid < 128) ((float*)(sm + BIASO(1)))[tid] = p.eb0[tid];
    __syncthreads();

    float c[64];
    zero64(c);

    // L0: e0 first K-half (A = x[row]), slot0
    copy_tile(sm, 1, T_E0B, tid);
    pass3<8, 8>(c, sb, sb + SLOT_HI(0), sb + SLOT_LO(0), m0, lane);
    __syncthreads();

    // regather A = x[col]; prefetch e1; bias eb1 for L2
    gather(sm, p.x, cols_s, e0, p.E, tid);
    copy_tile(sm, 0, T_E1, tid);
    if (tid < 128) ((float*)(sm + BIASO(0)))[tid] = p.eb1[tid];
    __syncthreads();

    // L1: e0 second K-half (accumulate), slot1; epi eb0
    pass3<8, 8>(c, sb, sb + SLOT_HI(1), sb + SLOT_LO(1), m0, lane);
    epi_hidden(c, sm, (float*)(sm + BIASO(1)), m0, lane);
    __syncthreads();

    // L2: e1, slot0; prefetch e2; bias eb2 for L3
    copy_tile(sm, 1, T_E2, tid);
    if (tid < 128) ((float*)(sm + BIASO(1)))[tid] = p.eb2[tid];
    zero64(c);
    pass3<8, 8>(c, sb, sb + SLOT_HI(0), sb + SLOT_LO(0), m0, lane);
    epi_hidden(c, sm, (float*)(sm + BIASO(0)), m0, lane);
    __syncthreads();

    // L3: e2, slot1; prefetch e3; bias db0 for L5
    copy_tile(sm, 0, T_E3, tid);
    if (tid < 128) ((float*)(sm + BIASO(0)))[tid] = p.db0[tid];
    zero64(c);
    pass3<8, 8>(c, sb, sb + SLOT_HI(1), sb + SLOT_LO(1), m0, lane);
    epi_hidden(c, sm, (float*)(sm + BIASO(1)), m0, lane);
    __syncthreads();

    // L4: e3 (N=16 incl. pad), slot0; prefetch d0; bias db1 for L6
    copy_tile(sm, 1, T_D0, tid);
    if (tid < 128) ((float*)(sm + BIASO(1)))[tid] = p.db1[tid];
    zero64(c);
    pass3<8, 1>(c, sb, sb + SLOT_HI(0), sb + SLOT_LO(0), m0, lane);
    // enc3 epilogue: stash c -> tmp, then per-edge reparam + KL, z -> A
    {
        float* tmp = (float*)(sm + TMPB);
        int g = lane >> 2, qp = lane & 3;
        #pragma unroll
        for (int nt = 0; nt < 2; nt++) {
            int col = nt * 8 + qp * 2;
            tmp[(m0 + g)     * 16 + col]     = c[nt*4+0];
            tmp[(m0 + g)     * 16 + col + 1] = c[nt*4+1];
            tmp[(m0 + g + 8) * 16 + col]     = c[nt*4+2];
            tmp[(m0 + g + 8) * 16 + col + 1] = c[nt*4+3];
        }
    }
    __syncthreads();
    if (tid < 128) {
        float* tmp = (float*)(sm + TMPB);
        int r = tid, e = e0 + r;
        bool v = e < p.E;
        float kl = 0.f;
        float z[5];
        #pragma unroll
        for (int l = 0; l < 5; l++) {
            float mu = tmp[r * 16 + l]     + p.eb3[l];
            float lv = tmp[r * 16 + 5 + l] + p.eb3[5 + l];
            float ep = v ? p.eps[(size_t)e * 5 + l] : 0.f;
            z[l] = fmaf(ep, expf(0.5f * lv), mu);
            kl  += -0.5f * (1.f + lv - mu * mu - expf(lv));
        }
        ((float*)(sm + KLP))[r] = v ? kl * BETA : 0.f;
        uint32_t h0, l0, h1, l1, h2, l2;
        split2(z[0], z[1], h0, l0);
        split2(z[2], z[3], h1, l1);
        split2(z[4], 0.f,  h2, l2);
        uint8_t* hp = sm + AHI + (size_t)r * STRIDE * 2;
        uint8_t* lp = sm + ALO + (size_t)r * STRIDE * 2;
        *(uint4*)(hp)      = make_uint4(h0, h1, h2, 0);
        *(uint4*)(hp + 16) = make_uint4(0, 0, 0, 0);
        *(uint4*)(lp)      = make_uint4(l0, l1, l2, 0);
        *(uint4*)(lp + 16) = make_uint4(0, 0, 0, 0);
    }
    __syncthreads();

    // L5: d0 (K=16), slot1; prefetch d1; epi db0
    copy_tile(sm, 0, T_D1, tid);
    zero64(c);
    pass3<1, 8>(c, sb, sb + SLOT_HI(1), sb + SLOT_LO(1), m0, lane);
    epi_hidden(c, sm, (float*)(sm + BIASO(0)), m0, lane);
    __syncthreads();

    // L6: d1, slot0; prefetch d2; bias db2 for L7; epi db1
    copy_tile(sm, 1, T_D2, tid);
    if (tid < 128) ((float*)(sm + BIASO(0)))[tid] = p.db2[tid];
    zero64(c);
    pass3<8, 8>(c, sb, sb + SLOT_HI(0), sb + SLOT_LO(0), m0, lane);
    epi_hidden(c, sm, (float*)(sm + BIASO(1)), m0, lane);
    __syncthreads();

    // L7: d2, slot1; prefetch d3a; bias db3[0:128] for L8; epi db2
    copy_tile(sm, 0, T_D3A, tid);
    if (tid < 128) ((float*)(sm + BIASO(1)))[tid] = p.db3[tid];
    zero64(c);
    pass3<8, 8>(c, sb, sb + SLOT_HI(1), sb + SLOT_LO(1), m0, lane);
    epi_hidden(c, sm, (float*)(sm + BIASO(0)), m0, lane);
    __syncthreads();

    // L8: d3a, slot0; prefetch d3b; bias db3[128:] for L9; recon vs x[row]
    copy_tile(sm, 1, T_D3B, tid);
    if (tid < 128) ((float*)(sm + BIASO(0)))[tid] = p.db3[128 + tid];
    zero64(c);
    pass3<8, 8>(c, sb, sb + SLOT_HI(0), sb + SLOT_LO(0), m0, lane);
    epi_recon(c, sm, (float*)(sm + BIASO(1)), p.x, rows_s, m0, lane);
    __syncthreads();

    // L9: d3b, slot1; recon vs x[col]
    zero64(c);
    pass3<8, 8>(c, sb, sb + SLOT_HI(1), sb + SLOT_LO(1), m0, lane);
    epi_recon(c, sm, (float*)(sm + BIASO(0)), p.x, cols_s, m0, lane);
    __syncthreads();

    // finalize: affinities + block reduction
    float rl = 0.f, kl = 0.f;
    if (tid < 128) {
        int e = e0 + tid;
        bool v = e < p.E;
        float ssq = ((float*)(sm + RS))[tid];
        rl = v ? sqrtf(ssq) : 0.f;
        kl = ((float*)(sm + KLP))[tid];
        if (v) p.out[e] = 1.0f / fmaf(V2C, rl, 1.0f);
    }
    float s1 = rl, s2 = kl;
    #pragma unroll
    for (int o = 16; o; o >>= 1) {
        s1 += __shfl_down_sync(0xFFFFFFFFu, s1, o);
        s2 += __shfl_down_sync(0xFFFFFFFFu, s2, o);
    }
    float* red = (float*)(sm + RED);
    if (lane == 0) { red[tid >> 5] = s1; red[8 + (tid >> 5)] = s2; }
    __syncthreads();
    if (tid == 0) {
        float a = 0.f, b = 0.f;
        #pragma unroll
        for (int i = 0; i < 8; i++) { a += red[i]; b += red[8 + i]; }
        atomicAdd(&g_rsum,  (double)a);
        atomicAdd(&g_klsum, (double)b);
    }
}

// ---------------------------------------------------------------------------
extern "C" void kernel_launch(void* const* d_in, const int* in_sizes, int n_in,
                              void* d_out, int out_size) {
    Params p;
    p.x   = (const float*)d_in[0];
    p.row = (const int*)  d_in[1];
    p.col = (const int*)  d_in[2];
    p.eps = (const float*)d_in[3];
    p.eW0 = (const float*)d_in[4];   p.eb0 = (const float*)d_in[5];
    p.eW1 = (const float*)d_in[6];   p.eb1 = (const float*)d_in[7];
    p.eW2 = (const float*)d_in[8];   p.eb2 = (const float*)d_in[9];
    p.eW3 = (const float*)d_in[10];  p.eb3 = (const float*)d_in[11];
    p.dW0 = (const float*)d_in[12];  p.db0 = (const float*)d_in[13];
    p.dW1 = (const float*)d_in[14];  p.db1 = (const float*)d_in[15];
    p.dW2 = (const float*)d_in[16];  p.db2 = (const float*)d_in[17];
    p.dW3 = (const float*)d_in[18];  p.db3 = (const float*)d_in[19];
    p.out = (float*)d_out;
    p.E   = in_sizes[1];

    cudaFuncSetAttribute(vae_kernel,
                         cudaFuncAttributeMaxDynamicSharedMemorySize, SMEM_TOTAL);

    const int tiles = (p.E + TT - 1) / TT;
    prep_kernel<<<64, 256>>>(p);
    vae_kernel<<<tiles, THREADS, SMEM_TOTAL>>>(p);
    fin_kernel<<<1, 1>>>((float*)d_out, p.E);
}

// round 5
// speedup vs baseline: 5.1548x; 2.2193x over previous
#include <cuda_runtime.h>
#include <cuda_fp16.h>
#include <cstdint>

#define THREADS 256
#define TT      128
#define STRIDE  136                 // fp16 elems per smem row (128 + 8 pad)
#define ROWB    (STRIDE * 2)        // 272 bytes per row
#define TSZ     (128 * STRIDE)      // elems per weight tile
#define BETA    10.0f
#define V2C     3.5f

__device__ double g_rsum, g_klsum;

// 10 weight tiles, fp16, [k][n] layout with row stride 136
enum { T_E0A, T_E0B, T_E1, T_E2, T_E3, T_D0, T_D1, T_D2, T_D3A, T_D3B };
__device__ __align__(16) uint16_t g_w[10 * TSZ];

// ---- smem byte offsets ----
#define AOFF      0
#define SLOT(s)   (34816 + (s) * 34816)
#define BIASO(b)  (104448 + (b) * 512)
#define ROWS_S    105472
#define COLS_S    105984
#define KLP       106496
#define RS        107008
#define RED       107520
#define SMEM_TOTAL 107584

struct Params {
    const float* x; const int* row; const int* col; const float* eps;
    const float *eW0,*eb0,*eW1,*eb1,*eW2,*eb2,*eW3,*eb3;
    const float *dW0,*db0,*dW1,*db1,*dW2,*db2,*dW3,*db3;
    float* out; int E;
};

// ---- helpers ----
__device__ __forceinline__ uint32_t smem_u32(const void* p) {
    uint32_t a;
    asm("{ .reg .u64 t; cvta.to.shared.u64 t, %1; cvt.u32.u64 %0, t; }" : "=r"(a) : "l"(p));
    return a;
}
__device__ __forceinline__ uint32_t pack_h2(float a, float b) {
    __half2 h = __floats2half2_rn(a, b);
    return *(uint32_t*)&h;
}

// A fragment: 16x16 row-major tile at (m0, k0) via ldmatrix.x4 (rows warp-private)
__device__ __forceinline__ void lda4(uint32_t a[4], uint32_t base, int m0, int k0, int lane) {
    uint32_t addr = base + (uint32_t)(((m0 + (lane & 7) + ((lane & 8) ? 8 : 0)) * STRIDE
                                   + k0 + ((lane & 16) ? 8 : 0)) << 1);
    asm volatile("ldmatrix.sync.aligned.m8n8.x4.shared.b16 {%0,%1,%2,%3}, [%4];"
        : "=r"(a[0]), "=r"(a[1]), "=r"(a[2]), "=r"(a[3]) : "r"(addr));
}

// B fragments: 16(k) x 16(n) tile at (k0, n0) via ldmatrix.x4.trans
__device__ __forceinline__ void ldb4t(uint32_t b[4], uint32_t base, int k0, int n0, int lane) {
    uint32_t addr = base + (uint32_t)(((k0 + (lane & 7) + ((lane & 8) ? 8 : 0)) * STRIDE
                                   + n0 + ((lane & 16) ? 8 : 0)) << 1);
    asm volatile("ldmatrix.sync.aligned.m8n8.x4.trans.shared.b16 {%0,%1,%2,%3}, [%4];"
        : "=r"(b[0]), "=r"(b[1]), "=r"(b[2]), "=r"(b[3]) : "r"(addr));
}

__device__ __forceinline__ void mma16816(float* c, const uint32_t a[4], uint32_t b0, uint32_t b1) {
    asm volatile("mma.sync.aligned.m16n8k16.row.col.f32.f16.f16.f32 "
        "{%0,%1,%2,%3}, {%4,%5,%6,%7}, {%8,%9}, {%0,%1,%2,%3};"
        : "+f"(c[0]), "+f"(c[1]), "+f"(c[2]), "+f"(c[3])
        : "r"(a[0]), "r"(a[1]), "r"(a[2]), "r"(a[3]), "r"(b0), "r"(b1));
}

// single-pass fp16 GEMM: c[16 rows x NT2*16 cols per warp] += A * B
template<int KS, int NT2>
__device__ __forceinline__ void gemm(float c[64], uint32_t abase, uint32_t bbase,
                                     int m0, int lane) {
    #pragma unroll 2
    for (int ks = 0; ks < KS; ks++) {
        uint32_t a[4];
        lda4(a, abase, m0, ks * 16, lane);
        #pragma unroll
        for (int q = 0; q < NT2; q++) {
            uint32_t b[4];
            ldb4t(b, bbase, ks * 16, q * 16, lane);
            mma16816(c + q * 8,     a, b[0], b[1]);
            mma16816(c + q * 8 + 4, a, b[2], b[3]);
        }
    }
}

__device__ __forceinline__ void zero64(float c[64]) {
    #pragma unroll
    for (int i = 0; i < 64; i++) c[i] = 0.f;
}

__device__ __forceinline__ void copy_tile(uint8_t* sm, int slot, int t, int tid) {
    const uint4* s = (const uint4*)(g_w + (size_t)t * TSZ);
    uint4* d = (uint4*)(sm + SLOT(slot));
    for (int i = tid; i < TSZ / 8; i += THREADS) d[i] = s[i];
}

// gather x[node] rows into A tile (fp16); 2 threads per row
__device__ __forceinline__ void gather(uint8_t* sm, const float* x, const int* nodes,
                                       int e0, int E, int tid) {
    int r = tid >> 1, half = tid & 1;
    bool v = (e0 + r) < E;
    int node = nodes[r];
    const float4* xr = (const float4*)(x + (size_t)node * 128 + half * 64);
    uint8_t* hp = sm + AOFF + (size_t)r * ROWB + half * 128;
    #pragma unroll
    for (int i = 0; i < 16; i++) {
        float4 f = v ? xr[i] : make_float4(0.f, 0.f, 0.f, 0.f);
        *(uint2*)(hp + i * 8) = make_uint2(pack_h2(f.x, f.y), pack_h2(f.z, f.w));
    }
}

// bias + relu -> A tile (fp16)
__device__ __forceinline__ void epi_hidden(const float c[64], uint8_t* sm,
                                           const float* bias, int m0, int lane) {
    int g = lane >> 2, qp = lane & 3;
    int r0 = m0 + g, r1 = m0 + g + 8;
    #pragma unroll
    for (int nt = 0; nt < 16; nt++) {
        int col = nt * 8 + qp * 2;
        float b0 = bias[col], b1 = bias[col + 1];
        float v0 = fmaxf(c[nt*4+0] + b0, 0.f), v1 = fmaxf(c[nt*4+1] + b1, 0.f);
        float v2 = fmaxf(c[nt*4+2] + b0, 0.f), v3 = fmaxf(c[nt*4+3] + b1, 0.f);
        *(uint32_t*)(sm + AOFF + (size_t)r0 * ROWB + col * 2) = pack_h2(v0, v1);
        *(uint32_t*)(sm + AOFF + (size_t)r1 * ROWB + col * 2) = pack_h2(v2, v3);
    }
}

// recon ssq epilogue for one d3 half
__device__ __forceinline__ void epi_recon(const float c[64], uint8_t* sm, const float* bias,
                                          const float* x, const int* nodes, int m0, int lane) {
    int g = lane >> 2, qp = lane & 3;
    int r0 = m0 + g, r1 = r0 + 8;
    const float* x0 = x + (size_t)nodes[r0] * 128;
    const float* x1 = x + (size_t)nodes[r1] * 128;
    float s0 = 0.f, s1 = 0.f;
    #pragma unroll
    for (int nt = 0; nt < 16; nt++) {
        int col = nt * 8 + qp * 2;
        float b0 = bias[col], b1 = bias[col + 1];
        float2 xa = *(const float2*)(x0 + col);
        float2 xb = *(const float2*)(x1 + col);
        float d0 = c[nt*4+0] + b0 - xa.x, d1 = c[nt*4+1] + b1 - xa.y;
        float d2 = c[nt*4+2] + b0 - xb.x, d3 = c[nt*4+3] + b1 - xb.y;
        s0 = fmaf(d0, d0, fmaf(d1, d1, s0));
        s1 = fmaf(d2, d2, fmaf(d3, d3, s1));
    }
    s0 += __shfl_xor_sync(0xFFFFFFFFu, s0, 1);
    s0 += __shfl_xor_sync(0xFFFFFFFFu, s0, 2);
    s1 += __shfl_xor_sync(0xFFFFFFFFu, s1, 1);
    s1 += __shfl_xor_sync(0xFFFFFFFFu, s1, 2);
    if (qp == 0) {
        float* rs = (float*)(sm + RS);
        rs[r0] += s0;
        rs[r1] += s1;
    }
}

// ---- weight prep ----
__device__ void prep_one(const float* W, int krows, int kstride, int noff, int ncols, int tile) {
    int total = krows * ncols;
    int gt = blockIdx.x * blockDim.x + threadIdx.x;
    int gs = gridDim.x * blockDim.x;
    for (int idx = gt; idx < total; idx += gs) {
        int k = idx / ncols, n = idx % ncols;
        float w = W[(size_t)k * kstride + noff + n];
        g_w[(size_t)tile * TSZ + (size_t)k * STRIDE + n] =
            __half_as_ushort(__float2half_rn(w));
    }
}

__global__ void prep_kernel(Params p) {
    if (blockIdx.x == 0 && threadIdx.x == 0) { g_rsum = 0.0; g_klsum = 0.0; }
    prep_one(p.eW0,             128, 128, 0,   128, T_E0A);
    prep_one(p.eW0 + 128 * 128, 128, 128, 0,   128, T_E0B);
    prep_one(p.eW1,             128, 128, 0,   128, T_E1);
    prep_one(p.eW2,             128, 128, 0,   128, T_E2);
    prep_one(p.eW3,             128, 10,  0,   10,  T_E3);
    prep_one(p.dW0,             5,   128, 0,   128, T_D0);
    prep_one(p.dW1,             128, 128, 0,   128, T_D1);
    prep_one(p.dW2,             128, 128, 0,   128, T_D2);
    prep_one(p.dW3,             128, 256, 0,   128, T_D3A);
    prep_one(p.dW3,             128, 256, 128, 128, T_D3B);
}

__global__ void fin_kernel(float* out, int E) {
    out[E]     = (float)(g_rsum  / (double)E);
    out[E + 1] = (float)(g_klsum / ((double)E * 5.0));
}

// ---- main fused VAE kernel: 1 CTA = 128 edges, 8 warps (16 rows each), 2 CTAs/SM ----
__global__ void __launch_bounds__(THREADS, 2)
vae_kernel(Params p) {
    extern __shared__ __align__(16) uint8_t sm[];
    const uint32_t sb = smem_u32(sm);
    const int tid  = threadIdx.x;
    const int lane = tid & 31;
    const int m0   = (tid >> 5) * 16;
    const int e0   = blockIdx.x * TT;

    int* rows_s = (int*)(sm + ROWS_S);
    int* cols_s = (int*)(sm + COLS_S);
    if (tid < 128) {
        int e = e0 + tid;
        bool v = e < p.E;
        rows_s[tid] = v ? p.row[e] : 0;
        cols_s[tid] = v ? p.col[e] : 0;
        ((float*)(sm + RS))[tid] = 0.f;
    }
    copy_tile(sm, 0, T_E0A, tid);
    __syncthreads();

    gather(sm, p.x, rows_s, e0, p.E, tid);
    if (tid < 128) ((float*)(sm + BIASO(1)))[tid] = p.eb0[tid];
    __syncthreads();

    float c[64];
    zero64(c);

    // L0: e0 first K-half (A = x[row]), slot0; prefetch e0b
    copy_tile(sm, 1, T_E0B, tid);
    gemm<8, 8>(c, sb + AOFF, sb + SLOT(0), m0, lane);
    __syncthreads();

    // regather A = x[col]; prefetch e1; bias eb1
    gather(sm, p.x, cols_s, e0, p.E, tid);
    copy_tile(sm, 0, T_E1, tid);
    if (tid < 128) ((float*)(sm + BIASO(0)))[tid] = p.eb1[tid];
    __syncthreads();

    // L1: e0 second K-half (accumulate), slot1; epi eb0
    gemm<8, 8>(c, sb + AOFF, sb + SLOT(1), m0, lane);
    epi_hidden(c, sm, (float*)(sm + BIASO(1)), m0, lane);
    __syncthreads();

    // L2: e1, slot0; prefetch e2; bias eb2
    copy_tile(sm, 1, T_E2, tid);
    if (tid < 128) ((float*)(sm + BIASO(1)))[tid] = p.eb2[tid];
    zero64(c);
    gemm<8, 8>(c, sb + AOFF, sb + SLOT(0), m0, lane);
    epi_hidden(c, sm, (float*)(sm + BIASO(0)), m0, lane);
    __syncthreads();

    // L3: e2, slot1; prefetch e3; bias db0
    copy_tile(sm, 0, T_E3, tid);
    if (tid < 128) ((float*)(sm + BIASO(0)))[tid] = p.db0[tid];
    zero64(c);
    gemm<8, 8>(c, sb + AOFF, sb + SLOT(1), m0, lane);
    epi_hidden(c, sm, (float*)(sm + BIASO(1)), m0, lane);
    __syncthreads();

    // L4: e3 (N=16 incl. pad), slot0; prefetch d0; bias db1
    copy_tile(sm, 1, T_D0, tid);
    if (tid < 128) ((float*)(sm + BIASO(1)))[tid] = p.db1[tid];
    zero64(c);
    gemm<8, 1>(c, sb + AOFF, sb + SLOT(0), m0, lane);
    // stash 16-wide result into warp-private A row tail (float cols 32..63 of fp16 space)
    {
        int g = lane >> 2, qp = lane & 3;
        int r0 = m0 + g, r1 = r0 + 8;
        #pragma unroll
        for (int nt = 0; nt < 2; nt++) {
            int col = nt * 8 + qp * 2;
            *(float2*)(sm + AOFF + (size_t)r0 * ROWB + 64 + col * 4) =
                make_float2(c[nt*4+0], c[nt*4+1]);
            *(float2*)(sm + AOFF + (size_t)r1 * ROWB + 64 + col * 4) =
                make_float2(c[nt*4+2], c[nt*4+3]);
        }
    }
    __syncthreads();
    // per-edge reparam + KL; z -> A cols 0..15 (fp16, zero-padded)
    if (tid < 128) {
        int r = tid, e = e0 + r;
        bool v = e < p.E;
        const float* tmp = (const float*)(sm + AOFF + (size_t)r * ROWB + 64);
        float kl = 0.f, z[5];
        #pragma unroll
        for (int l = 0; l < 5; l++) {
            float mu = tmp[l]     + p.eb3[l];
            float lv = tmp[5 + l] + p.eb3[5 + l];
            float ep = v ? p.eps[(size_t)e * 5 + l] : 0.f;
            z[l] = fmaf(ep, expf(0.5f * lv), mu);
            kl  += -0.5f * (1.f + lv - mu * mu - expf(lv));
        }
        ((float*)(sm + KLP))[r] = v ? kl * BETA : 0.f;
        uint8_t* hp = sm + AOFF + (size_t)r * ROWB;
        *(uint4*)(hp)      = make_uint4(pack_h2(z[0], z[1]), pack_h2(z[2], z[3]),
                                        pack_h2(z[4], 0.f), 0u);
        *(uint4*)(hp + 16) = make_uint4(0u, 0u, 0u, 0u);
    }
    __syncthreads();

    // L5: d0 (K=16), slot1; prefetch d1; epi db0
    copy_tile(sm, 0, T_D1, tid);
    zero64(c);
    gemm<1, 8>(c, sb + AOFF, sb + SLOT(1), m0, lane);
    epi_hidden(c, sm, (float*)(sm + BIASO(0)), m0, lane);
    __syncthreads();

    // L6: d1, slot0; prefetch d2; bias db2; epi db1
    copy_tile(sm, 1, T_D2, tid);
    if (tid < 128) ((float*)(sm + BIASO(0)))[tid] = p.db2[tid];
    zero64(c);
    gemm<8, 8>(c, sb + AOFF, sb + SLOT(0), m0, lane);
    epi_hidden(c, sm, (float*)(sm + BIASO(1)), m0, lane);
    __syncthreads();

    // L7: d2, slot1; prefetch d3a; bias db3[0:128]; epi db2
    copy_tile(sm, 0, T_D3A, tid);
    if (tid < 128) ((float*)(sm + BIASO(1)))[tid] = p.db3[tid];
    zero64(c);
    gemm<8, 8>(c, sb + AOFF, sb + SLOT(1), m0, lane);
    epi_hidden(c, sm, (float*)(sm + BIASO(0)), m0, lane);
    __syncthreads();

    // L8: d3a, slot0; prefetch d3b; bias db3[128:]; recon vs x[row]
    copy_tile(sm, 1, T_D3B, tid);
    if (tid < 128) ((float*)(sm + BIASO(0)))[tid] = p.db3[128 + tid];
    zero64(c);
    gemm<8, 8>(c, sb + AOFF, sb + SLOT(0), m0, lane);
    epi_recon(c, sm, (float*)(sm + BIASO(1)), p.x, rows_s, m0, lane);
    __syncthreads();

    // L9: d3b, slot1; recon vs x[col]
    zero64(c);
    gemm<8, 8>(c, sb + AOFF, sb + SLOT(1), m0, lane);
    epi_recon(c, sm, (float*)(sm + BIASO(0)), p.x, cols_s, m0, lane);
    __syncthreads();

    // finalize: affinities + block reduction
    float rl = 0.f, kl = 0.f;
    if (tid < 128) {
        int e = e0 + tid;
        bool v = e < p.E;
        float ssq = ((float*)(sm + RS))[tid];
        rl = v ? sqrtf(ssq) : 0.f;
        kl = ((float*)(sm + KLP))[tid];
        if (v) p.out[e] = 1.0f / fmaf(V2C, rl, 1.0f);
    }
    float s1 = rl, s2 = kl;
    #pragma unroll
    for (int o = 16; o; o >>= 1) {
        s1 += __shfl_down_sync(0xFFFFFFFFu, s1, o);
        s2 += __shfl_down_sync(0xFFFFFFFFu, s2, o);
    }
    float* red = (float*)(sm + RED);
    if (lane == 0) { red[tid >> 5] = s1; red[8 + (tid >> 5)] = s2; }
    __syncthreads();
    if (tid == 0) {
        float a = 0.f, b = 0.f;
        #pragma unroll
        for (int i = 0; i < 8; i++) { a += red[i]; b += red[8 + i]; }
        atomicAdd(&g_rsum,  (double)a);
        atomicAdd(&g_klsum, (double)b);
    }
}

// ---------------------------------------------------------------------------
extern "C" void kernel_launch(void* const* d_in, const int* in_sizes, int n_in,
                              void* d_out, int out_size) {
    Params p;
    p.x   = (const float*)d_in[0];
    p.row = (const int*)  d_in[1];
    p.col = (const int*)  d_in[2];
    p.eps = (const float*)d_in[3];
    p.eW0 = (const float*)d_in[4];   p.eb0 = (const float*)d_in[5];
    p.eW1 = (const float*)d_in[6];   p.eb1 = (const float*)d_in[7];
    p.eW2 = (const float*)d_in[8];   p.eb2 = (const float*)d_in[9];
    p.eW3 = (const float*)d_in[10];  p.eb3 = (const float*)d_in[11];
    p.dW0 = (const float*)d_in[12];  p.db0 = (const float*)d_in[13];
    p.dW1 = (const float*)d_in[14];  p.db1 = (const float*)d_in[15];
    p.dW2 = (const float*)d_in[16];  p.db2 = (const float*)d_in[17];
    p.dW3 = (const float*)d_in[18];  p.db3 = (const float*)d_in[19];
    p.out = (float*)d_out;
    p.E   = in_sizes[1];

    cudaFuncSetAttribute(vae_kernel,
                         cudaFuncAttributeMaxDynamicSharedMemorySize, SMEM_TOTAL);

    const int tiles = (p.E + TT - 1) / TT;
    prep_kernel<<<64, 256>>>(p);
    vae_kernel<<<tiles, THREADS, SMEM_TOTAL>>>(p);
    fin_kernel<<<1, 1>>>((float*)d_out, p.E);
}

// round 6
// speedup vs baseline: 6.6690x; 1.2937x over previous
#include <cuda_runtime.h>
#include <cuda_fp16.h>
#include <cstdint>

#define THREADS 256
#define TT      128
#define STRIDE  136                 // fp16 elems per smem row (128 + 8 pad)
#define ROWB    (STRIDE * 2)        // 272 bytes per row
#define TSZ     (128 * STRIDE)      // elems per weight tile
#define BETA    10.0f
#define V2C     3.5f

__device__ double g_rsum, g_klsum;

// 10 weight tiles, fp16, [k][n] layout with row stride 136
enum { T_E0A, T_E0B, T_E1, T_E2, T_E3, T_D0, T_D1, T_D2, T_D3A, T_D3B };
__device__ __align__(16) uint16_t g_w[10 * TSZ];

// ---- smem byte offsets ----
#define AOFF      0
#define SLOT(s)   (34816 + (s) * 34816)
#define BIASO(b)  (104448 + (b) * 512)
#define ROWS_S    105472
#define COLS_S    105984
#define KLP       106496
#define RS        107008
#define RED       107520
#define SMEM_TOTAL 107584

struct Params {
    const float* x; const int* row; const int* col; const float* eps;
    const float *eW0,*eb0,*eW1,*eb1,*eW2,*eb2,*eW3,*eb3;
    const float *dW0,*db0,*dW1,*db1,*dW2,*db2,*dW3,*db3;
    float* out; int E;
};

// ---- helpers ----
__device__ __forceinline__ uint32_t smem_u32(const void* p) {
    uint32_t a;
    asm("{ .reg .u64 t; cvta.to.shared.u64 t, %1; cvt.u32.u64 %0, t; }" : "=r"(a) : "l"(p));
    return a;
}
__device__ __forceinline__ uint32_t pack_h2(float a, float b) {
    __half2 h = __floats2half2_rn(a, b);
    return *(uint32_t*)&h;
}

// cp.async primitives
__device__ __forceinline__ void cp16(uint32_t dst, const void* src) {
    asm volatile("cp.async.cg.shared.global [%0], [%1], 16;" :: "r"(dst), "l"(src));
}
__device__ __forceinline__ void cp4(uint32_t dst, const void* src) {
    asm volatile("cp.async.ca.shared.global [%0], [%1], 4;" :: "r"(dst), "l"(src));
}
#define CP_COMMIT() asm volatile("cp.async.commit_group;" ::: "memory")
#define CP_WAIT0()  asm volatile("cp.async.wait_group 0;"  ::: "memory")

// A fragment: 16x16 row-major tile at (m0, k0) via ldmatrix.x4 (rows warp-private)
__device__ __forceinline__ void lda4(uint32_t a[4], uint32_t base, int m0, int k0, int lane) {
    uint32_t addr = base + (uint32_t)(((m0 + (lane & 7) + ((lane & 8) ? 8 : 0)) * STRIDE
                                   + k0 + ((lane & 16) ? 8 : 0)) << 1);
    asm volatile("ldmatrix.sync.aligned.m8n8.x4.shared.b16 {%0,%1,%2,%3}, [%4];"
        : "=r"(a[0]), "=r"(a[1]), "=r"(a[2]), "=r"(a[3]) : "r"(addr));
}

// B fragments: 16(k) x 16(n) tile at (k0, n0) via ldmatrix.x4.trans
__device__ __forceinline__ void ldb4t(uint32_t b[4], uint32_t base, int k0, int n0, int lane) {
    uint32_t addr = base + (uint32_t)(((k0 + (lane & 7) + ((lane & 8) ? 8 : 0)) * STRIDE
                                   + n0 + ((lane & 16) ? 8 : 0)) << 1);
    asm volatile("ldmatrix.sync.aligned.m8n8.x4.trans.shared.b16 {%0,%1,%2,%3}, [%4];"
        : "=r"(b[0]), "=r"(b[1]), "=r"(b[2]), "=r"(b[3]) : "r"(addr));
}

__device__ __forceinline__ void mma16816(float* c, const uint32_t a[4], uint32_t b0, uint32_t b1) {
    asm volatile("mma.sync.aligned.m16n8k16.row.col.f32.f16.f16.f32 "
        "{%0,%1,%2,%3}, {%4,%5,%6,%7}, {%8,%9}, {%0,%1,%2,%3};"
        : "+f"(c[0]), "+f"(c[1]), "+f"(c[2]), "+f"(c[3])
        : "r"(a[0]), "r"(a[1]), "r"(a[2]), "r"(a[3]), "r"(b0), "r"(b1));
}

// software-pipelined fp16 GEMM: c[16 rows x NT2*16 cols per warp] += A * B
template<int KS, int NT2>
__device__ __forceinline__ void gemm(float c[64], uint32_t abase, uint32_t bbase,
                                     int m0, int lane) {
    uint32_t a0[4], a1[4], b0[4], b1[4];
    lda4(a0, abase, m0, 0, lane);
    ldb4t(b0, bbase, 0, 0, lane);
    #pragma unroll
    for (int it = 0; it < KS * NT2; it++) {
        const int q   = it % NT2;
        const int ks  = it / NT2;
        const int it2 = it + 1;
        const int q2  = it2 % NT2;
        const int ks2 = it2 / NT2;
        uint32_t (&bc)[4] = (it  & 1) ? b1 : b0;
        uint32_t (&bn)[4] = (it  & 1) ? b0 : b1;
        uint32_t (&ac)[4] = (ks  & 1) ? a1 : a0;
        if (it2 < KS * NT2) {
            ldb4t(bn, bbase, ks2 * 16, q2 * 16, lane);
            if (q2 == 0) {
                if (ks2 & 1) lda4(a1, abase, m0, ks2 * 16, lane);
                else         lda4(a0, abase, m0, ks2 * 16, lane);
            }
        }
        mma16816(c + q * 8,     ac, bc[0], bc[1]);
        mma16816(c + q * 8 + 4, ac, bc[2], bc[3]);
    }
}

__device__ __forceinline__ void zero64(float c[64]) {
    #pragma unroll
    for (int i = 0; i < 64; i++) c[i] = 0.f;
}

// async weight tile copy (caller commits)
__device__ __forceinline__ void copy_tile(uint32_t sb, int slot, int t, int tid) {
    uint32_t dst = sb + SLOT(slot);
    const uint8_t* src = (const uint8_t*)(g_w + (size_t)t * TSZ);
    for (int i = tid; i < TSZ / 8; i += THREADS)
        cp16(dst + i * 16, src + i * 16);
}

// gather x[node] rows into A tile (fp16); 2 threads per row
__device__ __forceinline__ void gather(uint8_t* sm, const float* x, const int* nodes,
                                       int e0, int E, int tid) {
    int r = tid >> 1, half = tid & 1;
    bool v = (e0 + r) < E;
    int node = nodes[r];
    const float4* xr = (const float4*)(x + (size_t)node * 128 + half * 64);
    uint8_t* hp = sm + AOFF + (size_t)r * ROWB + half * 128;
    #pragma unroll
    for (int i = 0; i < 16; i++) {
        float4 f = v ? xr[i] : make_float4(0.f, 0.f, 0.f, 0.f);
        *(uint2*)(hp + i * 8) = make_uint2(pack_h2(f.x, f.y), pack_h2(f.z, f.w));
    }
}

// bias + relu -> A tile (fp16)
__device__ __forceinline__ void epi_hidden(const float c[64], uint8_t* sm,
                                           const float* bias, int m0, int lane) {
    int g = lane >> 2, qp = lane & 3;
    int r0 = m0 + g, r1 = m0 + g + 8;
    #pragma unroll
    for (int nt = 0; nt < 16; nt++) {
        int col = nt * 8 + qp * 2;
        float2 b = *(const float2*)(bias + col);
        float v0 = fmaxf(c[nt*4+0] + b.x, 0.f), v1 = fmaxf(c[nt*4+1] + b.y, 0.f);
        float v2 = fmaxf(c[nt*4+2] + b.x, 0.f), v3 = fmaxf(c[nt*4+3] + b.y, 0.f);
        *(uint32_t*)(sm + AOFF + (size_t)r0 * ROWB + col * 2) = pack_h2(v0, v1);
        *(uint32_t*)(sm + AOFF + (size_t)r1 * ROWB + col * 2) = pack_h2(v2, v3);
    }
}

// recon ssq epilogue for one d3 half
__device__ __forceinline__ void epi_recon(const float c[64], uint8_t* sm, const float* bias,
                                          const float* x, const int* nodes, int m0, int lane) {
    int g = lane >> 2, qp = lane & 3;
    int r0 = m0 + g, r1 = r0 + 8;
    const float* x0 = x + (size_t)nodes[r0] * 128;
    const float* x1 = x + (size_t)nodes[r1] * 128;
    float s0 = 0.f, s1 = 0.f;
    #pragma unroll
    for (int nt = 0; nt < 16; nt++) {
        int col = nt * 8 + qp * 2;
        float2 b = *(const float2*)(bias + col);
        float2 xa = *(const float2*)(x0 + col);
        float2 xb = *(const float2*)(x1 + col);
        float d0 = c[nt*4+0] + b.x - xa.x, d1 = c[nt*4+1] + b.y - xa.y;
        float d2 = c[nt*4+2] + b.x - xb.x, d3 = c[nt*4+3] + b.y - xb.y;
        s0 = fmaf(d0, d0, fmaf(d1, d1, s0));
        s1 = fmaf(d2, d2, fmaf(d3, d3, s1));
    }
    s0 += __shfl_xor_sync(0xFFFFFFFFu, s0, 1);
    s0 += __shfl_xor_sync(0xFFFFFFFFu, s0, 2);
    s1 += __shfl_xor_sync(0xFFFFFFFFu, s1, 1);
    s1 += __shfl_xor_sync(0xFFFFFFFFu, s1, 2);
    if (qp == 0) {
        float* rs = (float*)(sm + RS);
        rs[r0] += s0;
        rs[r1] += s1;
    }
}

// ---- weight prep ----
__device__ void prep_one(const float* W, int krows, int kstride, int noff, int ncols, int tile) {
    int total = krows * ncols;
    int gt = blockIdx.x * blockDim.x + threadIdx.x;
    int gs = gridDim.x * blockDim.x;
    for (int idx = gt; idx < total; idx += gs) {
        int k = idx / ncols, n = idx % ncols;
        float w = W[(size_t)k * kstride + noff + n];
        g_w[(size_t)tile * TSZ + (size_t)k * STRIDE + n] =
            __half_as_ushort(__float2half_rn(w));
    }
}

__global__ void prep_kernel(Params p) {
    if (blockIdx.x == 0 && threadIdx.x == 0) { g_rsum = 0.0; g_klsum = 0.0; }
    prep_one(p.eW0,             128, 128, 0,   128, T_E0A);
    prep_one(p.eW0 + 128 * 128, 128, 128, 0,   128, T_E0B);
    prep_one(p.eW1,             128, 128, 0,   128, T_E1);
    prep_one(p.eW2,             128, 128, 0,   128, T_E2);
    prep_one(p.eW3,             128, 10,  0,   10,  T_E3);
    prep_one(p.dW0,             5,   128, 0,   128, T_D0);
    prep_one(p.dW1,             128, 128, 0,   128, T_D1);
    prep_one(p.dW2,             128, 128, 0,   128, T_D2);
    prep_one(p.dW3,             128, 256, 0,   128, T_D3A);
    prep_one(p.dW3,             128, 256, 128, 128, T_D3B);
}

__global__ void fin_kernel(float* out, int E) {
    out[E]     = (float)(g_rsum  / (double)E);
    out[E + 1] = (float)(g_klsum / ((double)E * 5.0));
}

// ---- main fused VAE kernel: 1 CTA = 128 edges, 8 warps (16 rows each), 2 CTAs/SM ----
__global__ void __launch_bounds__(THREADS, 2)
vae_kernel(Params p) {
    extern __shared__ __align__(16) uint8_t sm[];
    const uint32_t sb = smem_u32(sm);
    const int tid  = threadIdx.x;
    const int lane = tid & 31;
    const int m0   = (tid >> 5) * 16;
    const int e0   = blockIdx.x * TT;

    int* rows_s = (int*)(sm + ROWS_S);
    int* cols_s = (int*)(sm + COLS_S);
    if (tid < 128) {
        int e = e0 + tid;
        bool v = e < p.E;
        rows_s[tid] = v ? p.row[e] : 0;
        cols_s[tid] = v ? p.col[e] : 0;
        ((float*)(sm + RS))[tid] = 0.f;
    }
    // async: slot0 <- E0A, bias eb0 -> BIASO(1)
    copy_tile(sb, 0, T_E0A, tid);
    if (tid < 128) cp4(sb + BIASO(1) + tid * 4, p.eb0 + tid);
    CP_COMMIT();
    __syncthreads();                 // rows_s/cols_s visible

    gather(sm, p.x, rows_s, e0, p.E, tid);
    CP_WAIT0();
    __syncthreads();                 // slot0 + eb0 + A(row) ready

    float c[64];
    zero64(c);

    // L0: e0 first K-half (A = x[row]), slot0; async slot1 <- E0B
    copy_tile(sb, 1, T_E0B, tid);
    CP_COMMIT();
    gemm<8, 8>(c, sb + AOFF, sb + SLOT(0), m0, lane);
    CP_WAIT0();
    __syncthreads();                 // all warps done reading A; slot1 ready

    // regather A = x[col]; async slot0 <- E1, bias eb1 -> BIASO(0)
    gather(sm, p.x, cols_s, e0, p.E, tid);
    copy_tile(sb, 0, T_E1, tid);
    if (tid < 128) cp4(sb + BIASO(0) + tid * 4, p.eb1 + tid);
    CP_COMMIT();
    __syncthreads();                 // A(col) visible

    // L1: e0 second K-half (accumulate), slot1; epi eb0
    gemm<8, 8>(c, sb + AOFF, sb + SLOT(1), m0, lane);
    epi_hidden(c, sm, (float*)(sm + BIASO(1)), m0, lane);
    CP_WAIT0();
    __syncthreads();

    // L2: e1, slot0; async slot1 <- E2, eb2 -> BIASO(1); epi eb1
    copy_tile(sb, 1, T_E2, tid);
    if (tid < 128) cp4(sb + BIASO(1) + tid * 4, p.eb2 + tid);
    CP_COMMIT();
    zero64(c);
    gemm<8, 8>(c, sb + AOFF, sb + SLOT(0), m0, lane);
    epi_hidden(c, sm, (float*)(sm + BIASO(0)), m0, lane);
    CP_WAIT0();
    __syncthreads();

    // L3: e2, slot1; async slot0 <- E3, db0 -> BIASO(0); epi eb2
    copy_tile(sb, 0, T_E3, tid);
    if (tid < 128) cp4(sb + BIASO(0) + tid * 4, p.db0 + tid);
    CP_COMMIT();
    zero64(c);
    gemm<8, 8>(c, sb + AOFF, sb + SLOT(1), m0, lane);
    epi_hidden(c, sm, (float*)(sm + BIASO(1)), m0, lane);
    CP_WAIT0();
    __syncthreads();

    // L4: e3 (N=16 incl. pad), slot0; async slot1 <- D0, db1 -> BIASO(1)
    copy_tile(sb, 1, T_D0, tid);
    if (tid < 128) cp4(sb + BIASO(1) + tid * 4, p.db1 + tid);
    CP_COMMIT();
    zero64(c);
    gemm<8, 1>(c, sb + AOFF, sb + SLOT(0), m0, lane);
    // stash 16-wide result into warp-private A row tail (bytes 64..127)
    {
        int g = lane >> 2, qp = lane & 3;
        int r0 = m0 + g, r1 = r0 + 8;
        #pragma unroll
        for (int nt = 0; nt < 2; nt++) {
            int col = nt * 8 + qp * 2;
            *(float2*)(sm + AOFF + (size_t)r0 * ROWB + 64 + col * 4) =
                make_float2(c[nt*4+0], c[nt*4+1]);
            *(float2*)(sm + AOFF + (size_t)r1 * ROWB + 64 + col * 4) =
                make_float2(c[nt*4+2], c[nt*4+3]);
        }
    }
    __syncthreads();
    // per-edge reparam + KL; z -> A cols 0..15 (fp16, zero-padded)
    if (tid < 128) {
        int r = tid, e = e0 + r;
        bool v = e < p.E;
        const float* tmp = (const float*)(sm + AOFF + (size_t)r * ROWB + 64);
        float kl = 0.f, z[5];
        #pragma unroll
        for (int l = 0; l < 5; l++) {
            float mu = tmp[l]     + p.eb3[l];
            float lv = tmp[5 + l] + p.eb3[5 + l];
            float ep = v ? p.eps[(size_t)e * 5 + l] : 0.f;
            z[l] = fmaf(ep, expf(0.5f * lv), mu);
            kl  += -0.5f * (1.f + lv - mu * mu - expf(lv));
        }
        ((float*)(sm + KLP))[r] = v ? kl * BETA : 0.f;
        uint8_t* hp = sm + AOFF + (size_t)r * ROWB;
        *(uint4*)(hp)      = make_uint4(pack_h2(z[0], z[1]), pack_h2(z[2], z[3]),
                                        pack_h2(z[4], 0.f), 0u);
        *(uint4*)(hp + 16) = make_uint4(0u, 0u, 0u, 0u);
    }
    CP_WAIT0();
    __syncthreads();

    // L5: d0 (K=16), slot1; async slot0 <- D1; epi db0
    copy_tile(sb, 0, T_D1, tid);
    CP_COMMIT();
    zero64(c);
    gemm<1, 8>(c, sb + AOFF, sb + SLOT(1), m0, lane);
    epi_hidden(c, sm, (float*)(sm + BIASO(0)), m0, lane);
    CP_WAIT0();
    __syncthreads();

    // L6: d1, slot0; async slot1 <- D2, db2 -> BIASO(0); epi db1
    copy_tile(sb, 1, T_D2, tid);
    if (tid < 128) cp4(sb + BIASO(0) + tid * 4, p.db2 + tid);
    CP_COMMIT();
    zero64(c);
    gemm<8, 8>(c, sb + AOFF, sb + SLOT(0), m0, lane);
    epi_hidden(c, sm, (float*)(sm + BIASO(1)), m0, lane);
    CP_WAIT0();
    __syncthreads();

    // L7: d2, slot1; async slot0 <- D3A, db3[0:128] -> BIASO(1); epi db2
    copy_tile(sb, 0, T_D3A, tid);
    if (tid < 128) cp4(sb + BIASO(1) + tid * 4, p.db3 + tid);
    CP_COMMIT();
    zero64(c);
    gemm<8, 8>(c, sb + AOFF, sb + SLOT(1), m0, lane);
    epi_hidden(c, sm, (float*)(sm + BIASO(0)), m0, lane);
    CP_WAIT0();
    __syncthreads();

    // L8: d3a, slot0; async slot1 <- D3B, db3[128:] -> BIASO(0); recon vs x[row]
    copy_tile(sb, 1, T_D3B, tid);
    if (tid < 128) cp4(sb + BIASO(0) + tid * 4, p.db3 + 128 + tid);
    CP_COMMIT();
    zero64(c);
    gemm<8, 8>(c, sb + AOFF, sb + SLOT(0), m0, lane);
    epi_recon(c, sm, (float*)(sm + BIASO(1)), p.x, rows_s, m0, lane);
    CP_WAIT0();
    __syncthreads();

    // L9: d3b, slot1; recon vs x[col]
    zero64(c);
    gemm<8, 8>(c, sb + AOFF, sb + SLOT(1), m0, lane);
    epi_recon(c, sm, (float*)(sm + BIASO(0)), p.x, cols_s, m0, lane);
    __syncthreads();

    // finalize: affinities + block reduction
    float rl = 0.f, kl = 0.f;
    if (tid < 128) {
        int e = e0 + tid;
        bool v = e < p.E;
        float ssq = ((float*)(sm + RS))[tid];
        rl = v ? sqrtf(ssq) : 0.f;
        kl = ((float*)(sm + KLP))[tid];
        if (v) p.out[e] = 1.0f / fmaf(V2C, rl, 1.0f);
    }
    float s1 = rl, s2 = kl;
    #pragma unroll
    for (int o = 16; o; o >>= 1) {
        s1 += __shfl_down_sync(0xFFFFFFFFu, s1, o);
        s2 += __shfl_down_sync(0xFFFFFFFFu, s2, o);
    }
    float* red = (float*)(sm + RED);
    if (lane == 0) { red[tid >> 5] = s1; red[8 + (tid >> 5)] = s2; }
    __syncthreads();
    if (tid == 0) {
        float a = 0.f, b = 0.f;
        #pragma unroll
        for (int i = 0; i < 8; i++) { a += red[i]; b += red[8 + i]; }
        atomicAdd(&g_rsum,  (double)a);
        atomicAdd(&g_klsum, (double)b);
    }
}

// ---------------------------------------------------------------------------
extern "C" void kernel_launch(void* const* d_in, const int* in_sizes, int n_in,
                              void* d_out, int out_size) {
    Params p;
    p.x   = (const float*)d_in[0];
    p.row = (const int*)  d_in[1];
    p.col = (const int*)  d_in[2];
    p.eps = (const float*)d_in[3];
    p.eW0 = (const float*)d_in[4];   p.eb0 = (const float*)d_in[5];
    p.eW1 = (const float*)d_in[6];   p.eb1 = (const float*)d_in[7];
    p.eW2 = (const float*)d_in[8];   p.eb2 = (const float*)d_in[9];
    p.eW3 = (const float*)d_in[10];  p.eb3 = (const float*)d_in[11];
    p.dW0 = (const float*)d_in[12];  p.db0 = (const float*)d_in[13];
    p.dW1 = (const float*)d_in[14];  p.db1 = (const float*)d_in[15];
    p.dW2 = (const float*)d_in[16];  p.db2 = (const float*)d_in[17];
    p.dW3 = (const float*)d_in[18];  p.db3 = (const float*)d_in[19];
    p.out = (float*)d_out;
    p.E   = in_sizes[1];

    cudaFuncSetAttribute(vae_kernel,
                         cudaFuncAttributeMaxDynamicSharedMemorySize, SMEM_TOTAL);

    const int tiles = (p.E + TT - 1) / TT;
    prep_kernel<<<64, 256>>>(p);
    vae_kernel<<<tiles, THREADS, SMEM_TOTAL>>>(p);
    fin_kernel<<<1, 1>>>((float*)d_out, p.E);
}

// round 7
// speedup vs baseline: 7.0971x; 1.0642x over previous
#include <cuda_runtime.h>
#include <cuda_fp16.h>
#include <cstdint>

#define THREADS 256
#define TT      128
#define STRIDE  136                 // fp16 elems per smem row (128 + 8 pad)
#define ROWB    (STRIDE * 2)        // 272 bytes per row
#define TSZ     (128 * STRIDE)      // elems per weight tile
#define BETA    10.0f
#define V2C     3.5f

__device__ double g_rsum, g_klsum;

// 10 weight tiles, fp16, [k][n] layout with row stride 136
enum { T_E0A, T_E0B, T_E1, T_E2, T_E3, T_D0, T_D1, T_D2, T_D3A, T_D3B };
__device__ __align__(16) uint16_t g_w[10 * TSZ];

// ---- smem byte offsets ----
#define AOFF      0
#define SLOT(s)   (34816 + (s) * 34816)
#define BIASO(b)  (104448 + (b) * 512)
#define ROWS_S    105472
#define COLS_S    105984
#define KLP       106496
#define RS        107008
#define RED       107520
#define SMEM_TOTAL 107584

struct Params {
    const float* x; const int* row; const int* col; const float* eps;
    const float *eW0,*eb0,*eW1,*eb1,*eW2,*eb2,*eW3,*eb3;
    const float *dW0,*db0,*dW1,*db1,*dW2,*db2,*dW3,*db3;
    float* out; int E;
};

// ---- helpers ----
__device__ __forceinline__ uint32_t smem_u32(const void* p) {
    uint32_t a;
    asm("{ .reg .u64 t; cvta.to.shared.u64 t, %1; cvt.u32.u64 %0, t; }" : "=r"(a) : "l"(p));
    return a;
}
__device__ __forceinline__ uint32_t pack_h2(float a, float b) {
    __half2 h = __floats2half2_rn(a, b);
    return *(uint32_t*)&h;
}

// cp.async primitives
__device__ __forceinline__ void cp16(uint32_t dst, const void* src) {
    asm volatile("cp.async.cg.shared.global [%0], [%1], 16;" :: "r"(dst), "l"(src));
}
__device__ __forceinline__ void cp4(uint32_t dst, const void* src) {
    asm volatile("cp.async.ca.shared.global [%0], [%1], 4;" :: "r"(dst), "l"(src));
}
#define CP_COMMIT() asm volatile("cp.async.commit_group;" ::: "memory")
#define CP_WAIT0()  asm volatile("cp.async.wait_group 0;"  ::: "memory")

// A fragment: 16x16 row-major tile at (m0, k0) via ldmatrix.x4
__device__ __forceinline__ void lda4(uint32_t a[4], uint32_t base, int m0, int k0, int lane) {
    uint32_t addr = base + (uint32_t)(((m0 + (lane & 7) + ((lane & 8) ? 8 : 0)) * STRIDE
                                   + k0 + ((lane & 16) ? 8 : 0)) << 1);
    asm volatile("ldmatrix.sync.aligned.m8n8.x4.shared.b16 {%0,%1,%2,%3}, [%4];"
        : "=r"(a[0]), "=r"(a[1]), "=r"(a[2]), "=r"(a[3]) : "r"(addr));
}

// B fragments: 16(k) x 16(n) tile at (k0, n0) via ldmatrix.x4.trans
__device__ __forceinline__ void ldb4t(uint32_t b[4], uint32_t base, int k0, int n0, int lane) {
    uint32_t addr = base + (uint32_t)(((k0 + (lane & 7) + ((lane & 8) ? 8 : 0)) * STRIDE
                                   + n0 + ((lane & 16) ? 8 : 0)) << 1);
    asm volatile("ldmatrix.sync.aligned.m8n8.x4.trans.shared.b16 {%0,%1,%2,%3}, [%4];"
        : "=r"(b[0]), "=r"(b[1]), "=r"(b[2]), "=r"(b[3]) : "r"(addr));
}

__device__ __forceinline__ void mma16816(float* c, const uint32_t a[4], uint32_t b0, uint32_t b1) {
    asm volatile("mma.sync.aligned.m16n8k16.row.col.f32.f16.f16.f32 "
        "{%0,%1,%2,%3}, {%4,%5,%6,%7}, {%8,%9}, {%0,%1,%2,%3};"
        : "+f"(c[0]), "+f"(c[1]), "+f"(c[2]), "+f"(c[3])
        : "r"(a[0]), "r"(a[1]), "r"(a[2]), "r"(a[3]), "r"(b0), "r"(b1));
}

// software-pipelined fp16 GEMM with A from SMEM (used for L0/L1 gathers + L5 z)
template<int KS, int NT2>
__device__ __forceinline__ void gemm(float c[64], uint32_t abase, uint32_t bbase,
                                     int m0, int lane) {
    uint32_t a0[4], a1[4], b0[4], b1[4];
    lda4(a0, abase, m0, 0, lane);
    ldb4t(b0, bbase, 0, 0, lane);
    #pragma unroll
    for (int it = 0; it < KS * NT2; it++) {
        const int q   = it % NT2;
        const int it2 = it + 1;
        const int q2  = it2 % NT2;
        const int ks2 = it2 / NT2;
        const int ks  = it / NT2;
        uint32_t (&bc)[4] = (it  & 1) ? b1 : b0;
        uint32_t (&bn)[4] = (it  & 1) ? b0 : b1;
        uint32_t (&ac)[4] = (ks  & 1) ? a1 : a0;
        if (it2 < KS * NT2) {
            ldb4t(bn, bbase, ks2 * 16, q2 * 16, lane);
            if (q2 == 0) {
                if (ks2 & 1) lda4(a1, abase, m0, ks2 * 16, lane);
                else         lda4(a0, abase, m0, ks2 * 16, lane);
            }
        }
        mma16816(c + q * 8,     ac, bc[0], bc[1]);
        mma16816(c + q * 8 + 4, ac, bc[2], bc[3]);
    }
}

// GEMM with A resident in registers (activation chain): full 128 cols
__device__ __forceinline__ void gemm_regA(float c[64], const uint32_t areg[32],
                                          uint32_t bbase, int lane) {
    uint32_t b0[4], b1[4];
    ldb4t(b0, bbase, 0, 0, lane);
    #pragma unroll
    for (int it = 0; it < 64; it++) {
        const int q  = it & 7;
        const int ks = it >> 3;
        uint32_t (&bc)[4] = (it & 1) ? b1 : b0;
        uint32_t (&bn)[4] = (it & 1) ? b0 : b1;
        if (it + 1 < 64)
            ldb4t(bn, bbase, ((it + 1) >> 3) * 16, ((it + 1) & 7) * 16, lane);
        const uint32_t* a = areg + ks * 4;
        mma16816(c + q * 8,     a, bc[0], bc[1]);
        mma16816(c + q * 8 + 4, a, bc[2], bc[3]);
    }
}

// GEMM regA, N=16 only (e3 layer)
__device__ __forceinline__ void gemm_regA_n16(float c[64], const uint32_t areg[32],
                                              uint32_t bbase, int lane) {
    uint32_t b0[4], b1[4];
    ldb4t(b0, bbase, 0, 0, lane);
    #pragma unroll
    for (int ks = 0; ks < 8; ks++) {
        uint32_t (&bc)[4] = (ks & 1) ? b1 : b0;
        uint32_t (&bn)[4] = (ks & 1) ? b0 : b1;
        if (ks + 1 < 8) ldb4t(bn, bbase, (ks + 1) * 16, 0, lane);
        const uint32_t* a = areg + ks * 4;
        mma16816(c,     a, bc[0], bc[1]);
        mma16816(c + 4, a, bc[2], bc[3]);
    }
}

__device__ __forceinline__ void zero64(float c[64]) {
    #pragma unroll
    for (int i = 0; i < 64; i++) c[i] = 0.f;
}

// bias + relu + pack: C fragments -> next-layer A fragments, all in registers.
// C lane layout == A lane layout for m16n8k16 (row g / g+8, cols/k 2qp,2qp+1).
__device__ __forceinline__ void epi_pack(const float c[64], uint32_t areg[32],
                                         const float* bias, int lane) {
    const int qp = lane & 3;
    #pragma unroll
    for (int ks = 0; ks < 8; ks++) {
        float2 bA = *(const float2*)(bias + 16 * ks + 2 * qp);
        float2 bB = *(const float2*)(bias + 16 * ks + 8 + 2 * qp);
        areg[ks*4+0] = pack_h2(fmaxf(c[8*ks+0] + bA.x, 0.f), fmaxf(c[8*ks+1] + bA.y, 0.f));
        areg[ks*4+1] = pack_h2(fmaxf(c[8*ks+2] + bA.x, 0.f), fmaxf(c[8*ks+3] + bA.y, 0.f));
        areg[ks*4+2] = pack_h2(fmaxf(c[8*ks+4] + bB.x, 0.f), fmaxf(c[8*ks+5] + bB.y, 0.f));
        areg[ks*4+3] = pack_h2(fmaxf(c[8*ks+6] + bB.x, 0.f), fmaxf(c[8*ks+7] + bB.y, 0.f));
    }
}

// async weight tile copy (caller commits)
__device__ __forceinline__ void copy_tile(uint32_t sb, int slot, int t, int tid) {
    uint32_t dst = sb + SLOT(slot);
    const uint8_t* src = (const uint8_t*)(g_w + (size_t)t * TSZ);
    for (int i = tid; i < TSZ / 8; i += THREADS)
        cp16(dst + i * 16, src + i * 16);
}

// gather x[node] rows into A tile (fp16); 2 threads per row
__device__ __forceinline__ void gather(uint8_t* sm, const float* x, const int* nodes,
                                       int e0, int E, int tid) {
    int r = tid >> 1, half = tid & 1;
    bool v = (e0 + r) < E;
    int node = nodes[r];
    const float4* xr = (const float4*)(x + (size_t)node * 128 + half * 64);
    uint8_t* hp = sm + AOFF + (size_t)r * ROWB + half * 128;
    #pragma unroll
    for (int i = 0; i < 16; i++) {
        float4 f = v ? xr[i] : make_float4(0.f, 0.f, 0.f, 0.f);
        *(uint2*)(hp + i * 8) = make_uint2(pack_h2(f.x, f.y), pack_h2(f.z, f.w));
    }
}

// recon ssq epilogue for one d3 half
__device__ __forceinline__ void epi_recon(const float c[64], uint8_t* sm, const float* bias,
                                          const float* x, const int* nodes, int m0, int lane) {
    int g = lane >> 2, qp = lane & 3;
    int r0 = m0 + g, r1 = r0 + 8;
    const float* x0 = x + (size_t)nodes[r0] * 128;
    const float* x1 = x + (size_t)nodes[r1] * 128;
    float s0 = 0.f, s1 = 0.f;
    #pragma unroll
    for (int nt = 0; nt < 16; nt++) {
        int col = nt * 8 + qp * 2;
        float2 b = *(const float2*)(bias + col);
        float2 xa = *(const float2*)(x0 + col);
        float2 xb = *(const float2*)(x1 + col);
        float d0 = c[nt*4+0] + b.x - xa.x, d1 = c[nt*4+1] + b.y - xa.y;
        float d2 = c[nt*4+2] + b.x - xb.x, d3 = c[nt*4+3] + b.y - xb.y;
        s0 = fmaf(d0, d0, fmaf(d1, d1, s0));
        s1 = fmaf(d2, d2, fmaf(d3, d3, s1));
    }
    s0 += __shfl_xor_sync(0xFFFFFFFFu, s0, 1);
    s0 += __shfl_xor_sync(0xFFFFFFFFu, s0, 2);
    s1 += __shfl_xor_sync(0xFFFFFFFFu, s1, 1);
    s1 += __shfl_xor_sync(0xFFFFFFFFu, s1, 2);
    if (qp == 0) {
        float* rs = (float*)(sm + RS);
        rs[r0] += s0;
        rs[r1] += s1;
    }
}

// ---- weight prep ----
__device__ void prep_one(const float* W, int krows, int kstride, int noff, int ncols, int tile) {
    int total = krows * ncols;
    int gt = blockIdx.x * blockDim.x + threadIdx.x;
    int gs = gridDim.x * blockDim.x;
    for (int idx = gt; idx < total; idx += gs) {
        int k = idx / ncols, n = idx % ncols;
        float w = W[(size_t)k * kstride + noff + n];
        g_w[(size_t)tile * TSZ + (size_t)k * STRIDE + n] =
            __half_as_ushort(__float2half_rn(w));
    }
}

__global__ void prep_kernel(Params p) {
    if (blockIdx.x == 0 && threadIdx.x == 0) { g_rsum = 0.0; g_klsum = 0.0; }
    prep_one(p.eW0,             128, 128, 0,   128, T_E0A);
    prep_one(p.eW0 + 128 * 128, 128, 128, 0,   128, T_E0B);
    prep_one(p.eW1,             128, 128, 0,   128, T_E1);
    prep_one(p.eW2,             128, 128, 0,   128, T_E2);
    prep_one(p.eW3,             128, 10,  0,   10,  T_E3);
    prep_one(p.dW0,             5,   128, 0,   128, T_D0);
    prep_one(p.dW1,             128, 128, 0,   128, T_D1);
    prep_one(p.dW2,             128, 128, 0,   128, T_D2);
    prep_one(p.dW3,             128, 256, 0,   128, T_D3A);
    prep_one(p.dW3,             128, 256, 128, 128, T_D3B);
}

__global__ void fin_kernel(float* out, int E) {
    out[E]     = (float)(g_rsum  / (double)E);
    out[E + 1] = (float)(g_klsum / ((double)E * 5.0));
}

// ---- main fused VAE kernel: 1 CTA = 128 edges, 8 warps (16 rows each), 2 CTAs/SM ----
__global__ void __launch_bounds__(THREADS, 2)
vae_kernel(Params p) {
    extern __shared__ __align__(16) uint8_t sm[];
    const uint32_t sb = smem_u32(sm);
    const int tid  = threadIdx.x;
    const int lane = tid & 31;
    const int m0   = (tid >> 5) * 16;
    const int e0   = blockIdx.x * TT;

    int* rows_s = (int*)(sm + ROWS_S);
    int* cols_s = (int*)(sm + COLS_S);
    if (tid < 128) {
        int e = e0 + tid;
        bool v = e < p.E;
        rows_s[tid] = v ? p.row[e] : 0;
        cols_s[tid] = v ? p.col[e] : 0;
        ((float*)(sm + RS))[tid] = 0.f;
    }
    // async: slot0 <- E0A, bias eb0 -> BIASO(1)
    copy_tile(sb, 0, T_E0A, tid);
    if (tid < 128) cp4(sb + BIASO(1) + tid * 4, p.eb0 + tid);
    CP_COMMIT();
    __syncthreads();

    gather(sm, p.x, rows_s, e0, p.E, tid);
    CP_WAIT0();
    __syncthreads();

    float c[64];
    uint32_t areg[32];
    zero64(c);

    // L0: e0 first K-half (A = x[row] smem), slot0; async slot1 <- E0B
    copy_tile(sb, 1, T_E0B, tid);
    CP_COMMIT();
    gemm<8, 8>(c, sb + AOFF, sb + SLOT(0), m0, lane);
    CP_WAIT0();
    __syncthreads();

    // regather A = x[col]; async slot0 <- E1, bias eb1 -> BIASO(0)
    gather(sm, p.x, cols_s, e0, p.E, tid);
    copy_tile(sb, 0, T_E1, tid);
    if (tid < 128) cp4(sb + BIASO(0) + tid * 4, p.eb1 + tid);
    CP_COMMIT();
    __syncthreads();

    // L1: e0 second K-half (accumulate), slot1; epi_pack eb0 -> areg
    gemm<8, 8>(c, sb + AOFF, sb + SLOT(1), m0, lane);
    epi_pack(c, areg, (float*)(sm + BIASO(1)), lane);
    CP_WAIT0();
    __syncthreads();

    // L2: e1, slot0 (A in regs); async slot1 <- E2, eb2 -> BIASO(1); epi_pack eb1
    copy_tile(sb, 1, T_E2, tid);
    if (tid < 128) cp4(sb + BIASO(1) + tid * 4, p.eb2 + tid);
    CP_COMMIT();
    zero64(c);
    gemm_regA(c, areg, sb + SLOT(0), lane);
    epi_pack(c, areg, (float*)(sm + BIASO(0)), lane);
    CP_WAIT0();
    __syncthreads();

    // L3: e2, slot1 (regs); async slot0 <- E3, db0 -> BIASO(0); epi_pack eb2
    copy_tile(sb, 0, T_E3, tid);
    if (tid < 128) cp4(sb + BIASO(0) + tid * 4, p.db0 + tid);
    CP_COMMIT();
    zero64(c);
    gemm_regA(c, areg, sb + SLOT(1), lane);
    epi_pack(c, areg, (float*)(sm + BIASO(1)), lane);
    CP_WAIT0();
    __syncthreads();

    // L4: e3 (N=16 incl. pad), slot0 (regs); async slot1 <- D0, db1 -> BIASO(1)
    copy_tile(sb, 1, T_D0, tid);
    if (tid < 128) cp4(sb + BIASO(1) + tid * 4, p.db1 + tid);
    CP_COMMIT();
    zero64(c);
    gemm_regA_n16(c, areg, sb + SLOT(0), lane);
    // stash 16-wide result into warp-private A row tail (bytes 64..127)
    {
        int g = lane >> 2, qp = lane & 3;
        int r0 = m0 + g, r1 = r0 + 8;
        #pragma unroll
        for (int nt = 0; nt < 2; nt++) {
            int col = nt * 8 + qp * 2;
            *(float2*)(sm + AOFF + (size_t)r0 * ROWB + 64 + col * 4) =
                make_float2(c[nt*4+0], c[nt*4+1]);
            *(float2*)(sm + AOFF + (size_t)r1 * ROWB + 64 + col * 4) =
                make_float2(c[nt*4+2], c[nt*4+3]);
        }
    }
    __syncthreads();
    // per-edge reparam + KL; z -> A cols 0..15 (fp16, zero-padded)
    if (tid < 128) {
        int r = tid, e = e0 + r;
        bool v = e < p.E;
        const float* tmp = (const float*)(sm + AOFF + (size_t)r * ROWB + 64);
        float kl = 0.f, z[5];
        #pragma unroll
        for (int l = 0; l < 5; l++) {
            float mu = tmp[l]     + p.eb3[l];
            float lv = tmp[5 + l] + p.eb3[5 + l];
            float ep = v ? p.eps[(size_t)e * 5 + l] : 0.f;
            z[l] = fmaf(ep, expf(0.5f * lv), mu);
            kl  += -0.5f * (1.f + lv - mu * mu - expf(lv));
        }
        ((float*)(sm + KLP))[r] = v ? kl * BETA : 0.f;
        uint8_t* hp = sm + AOFF + (size_t)r * ROWB;
        *(uint4*)(hp)      = make_uint4(pack_h2(z[0], z[1]), pack_h2(z[2], z[3]),
                                        pack_h2(z[4], 0.f), 0u);
        *(uint4*)(hp + 16) = make_uint4(0u, 0u, 0u, 0u);
    }
    CP_WAIT0();
    __syncthreads();

    // L5: d0 (K=16, A = z smem), slot1; async slot0 <- D1; epi_pack db0
    copy_tile(sb, 0, T_D1, tid);
    CP_COMMIT();
    zero64(c);
    gemm<1, 8>(c, sb + AOFF, sb + SLOT(1), m0, lane);
    epi_pack(c, areg, (float*)(sm + BIASO(0)), lane);
    CP_WAIT0();
    __syncthreads();

    // L6: d1, slot0 (regs); async slot1 <- D2, db2 -> BIASO(0); epi_pack db1
    copy_tile(sb, 1, T_D2, tid);
    if (tid < 128) cp4(sb + BIASO(0) + tid * 4, p.db2 + tid);
    CP_COMMIT();
    zero64(c);
    gemm_regA(c, areg, sb + SLOT(0), lane);
    epi_pack(c, areg, (float*)(sm + BIASO(1)), lane);
    CP_WAIT0();
    __syncthreads();

    // L7: d2, slot1 (regs); async slot0 <- D3A, db3[0:128] -> BIASO(1); epi_pack db2
    copy_tile(sb, 0, T_D3A, tid);
    if (tid < 128) cp4(sb + BIASO(1) + tid * 4, p.db3 + tid);
    CP_COMMIT();
    zero64(c);
    gemm_regA(c, areg, sb + SLOT(1), lane);
    epi_pack(c, areg, (float*)(sm + BIASO(0)), lane);
    CP_WAIT0();
    __syncthreads();

    // L8: d3a, slot0 (regs, areg preserved); async slot1 <- D3B, db3[128:] -> BIASO(0)
    copy_tile(sb, 1, T_D3B, tid);
    if (tid < 128) cp4(sb + BIASO(0) + tid * 4, p.db3 + 128 + tid);
    CP_COMMIT();
    zero64(c);
    gemm_regA(c, areg, sb + SLOT(0), lane);
    epi_recon(c, sm, (float*)(sm + BIASO(1)), p.x, rows_s, m0, lane);
    CP_WAIT0();
    __syncthreads();

    // L9: d3b, slot1 (same areg); recon vs x[col]
    zero64(c);
    gemm_regA(c, areg, sb + SLOT(1), lane);
    epi_recon(c, sm, (float*)(sm + BIASO(0)), p.x, cols_s, m0, lane);
    __syncthreads();

    // finalize: affinities + block reduction
    float rl = 0.f, kl = 0.f;
    if (tid < 128) {
        int e = e0 + tid;
        bool v = e < p.E;
        float ssq = ((float*)(sm + RS))[tid];
        rl = v ? sqrtf(ssq) : 0.f;
        kl = ((float*)(sm + KLP))[tid];
        if (v) p.out[e] = 1.0f / fmaf(V2C, rl, 1.0f);
    }
    float s1 = rl, s2 = kl;
    #pragma unroll
    for (int o = 16; o; o >>= 1) {
        s1 += __shfl_down_sync(0xFFFFFFFFu, s1, o);
        s2 += __shfl_down_sync(0xFFFFFFFFu, s2, o);
    }
    float* red = (float*)(sm + RED);
    if (lane == 0) { red[tid >> 5] = s1; red[8 + (tid >> 5)] = s2; }
    __syncthreads();
    if (tid == 0) {
        float a = 0.f, b = 0.f;
        #pragma unroll
        for (int i = 0; i < 8; i++) { a += red[i]; b += red[8 + i]; }
        atomicAdd(&g_rsum,  (double)a);
        atomicAdd(&g_klsum, (double)b);
    }
}

// ---------------------------------------------------------------------------
extern "C" void kernel_launch(void* const* d_in, const int* in_sizes, int n_in,
                              void* d_out, int out_size) {
    Params p;
    p.x   = (const float*)d_in[0];
    p.row = (const int*)  d_in[1];
    p.col = (const int*)  d_in[2];
    p.eps = (const float*)d_in[3];
    p.eW0 = (const float*)d_in[4];   p.eb0 = (const float*)d_in[5];
    p.eW1 = (const float*)d_in[6];   p.eb1 = (const float*)d_in[7];
    p.eW2 = (const float*)d_in[8];   p.eb2 = (const float*)d_in[9];
    p.eW3 = (const float*)d_in[10];  p.eb3 = (const float*)d_in[11];
    p.dW0 = (const float*)d_in[12];  p.db0 = (const float*)d_in[13];
    p.dW1 = (const float*)d_in[14];  p.db1 = (const float*)d_in[15];
    p.dW2 = (const float*)d_in[16];  p.db2 = (const float*)d_in[17];
    p.dW3 = (const float*)d_in[18];  p.db3 = (const float*)d_in[19];
    p.out = (float*)d_out;
    p.E   = in_sizes[1];

    cudaFuncSetAttribute(vae_kernel,
                         cudaFuncAttributeMaxDynamicSharedMemorySize, SMEM_TOTAL);

    const int tiles = (p.E + TT - 1) / TT;
    prep_kernel<<<64, 256>>>(p);
    vae_kernel<<<tiles, THREADS, SMEM_TOTAL>>>(p);
    fin_kernel<<<1, 1>>>((float*)d_out, p.E);
}